// round 1
// baseline (speedup 1.0000x reference)
#include <cuda_runtime.h>

#define NH 16
#define SEQ 2048
#define HD 64
#define BM 64
#define BN 64
#define NKT (SEQ / BN)
#define PITCH 65
#define SMEM_FLOATS (4 * HD * PITCH + BN * HD)
#define SMEM_BYTES (SMEM_FLOATS * 4)

__device__ float g_sum[NH];
__device__ float g_sumsq[NH];
__device__ float g_lam;

__device__ __forceinline__ float ex2(float x) {
    float r;
    asm("ex2.approx.ftz.f32 %0, %1;" : "=f"(r) : "f"(x));
    return r;
}

// ---------------------------------------------------------------------------
// Kernel 0: zero the per-head accumulators, compute lambda scalar.
// ---------------------------------------------------------------------------
__global__ void init_kernel(const float* __restrict__ lq1, const float* __restrict__ lq2,
                            const float* __restrict__ lk1, const float* __restrict__ lk2) {
    int t = threadIdx.x;  // 32 threads
    if (t < NH) { g_sum[t] = 0.f; g_sumsq[t] = 0.f; }
    float a = lq1[t] * lk1[t] + lq1[t + 32] * lk1[t + 32];
    float b = lq2[t] * lk2[t] + lq2[t + 32] * lk2[t + 32];
#pragma unroll
    for (int o = 16; o > 0; o >>= 1) {
        a += __shfl_xor_sync(0xffffffffu, a, o);
        b += __shfl_xor_sync(0xffffffffu, b, o);
    }
    if (t == 0) g_lam = __expf(a) - __expf(b) + 0.8f;
}

// ---------------------------------------------------------------------------
// Kernel 1: dual flash attention + combine. Writes raw (pre-layernorm) output
// and per-head sum / sumsq via atomics.
// ---------------------------------------------------------------------------
__global__ __launch_bounds__(256, 2) void attn_kernel(
    const float* __restrict__ q, const float* __restrict__ k,
    const float* __restrict__ v, float* __restrict__ out) {
    extern __shared__ float sm[];
    float* sQ1 = sm;                   // [HD][PITCH] transposed, pre-scaled
    float* sQ2 = sQ1 + HD * PITCH;
    float* sKP1 = sQ2 + HD * PITCH;    // K1 transposed, aliased with P1 transposed
    float* sKP2 = sKP1 + HD * PITCH;   // K2 transposed, aliased with P2 transposed
    float* sV = sKP2 + HD * PITCH;     // [BN][HD] natural

    const int tid = threadIdx.x;
    const int tx = tid & 15;
    const int ty = tid >> 4;
    const int h = blockIdx.y;
    const int qbase = blockIdx.x * BM;

    // scale * log2(e) = (1/8) * 1.4426950408889634
    const float C = 0.18033688011112042f;

    const float* qh = q + (size_t)h * SEQ * 2 * HD;
    const float* kh = k + (size_t)h * SEQ * 2 * HD;
    const float* vh = v + (size_t)h * SEQ * HD;

    // Load Q tile, transpose into smem, fold softmax scale (log2 domain) in.
    for (int e = tid; e < BM * 32; e += 256) {
        int s = e >> 5;
        int c4 = e & 31;
        float4 val = *(const float4*)(qh + (size_t)(qbase + s) * 2 * HD + c4 * 4);
        float* dst = (c4 < 16) ? sQ1 : sQ2;
        int d0 = (c4 & 15) * 4;
        dst[(d0 + 0) * PITCH + s] = val.x * C;
        dst[(d0 + 1) * PITCH + s] = val.y * C;
        dst[(d0 + 2) * PITCH + s] = val.z * C;
        dst[(d0 + 3) * PITCH + s] = val.w * C;
    }

    float acc1[4][4] = {}, acc2[4][4] = {};
    float m1[4], l1[4], m2[4], l2[4];
#pragma unroll
    for (int i = 0; i < 4; i++) { m1[i] = -1e30f; m2[i] = -1e30f; l1[i] = 0.f; l2[i] = 0.f; }

    for (int kt = 0; kt < NKT; kt++) {
        const int kbase = kt * BN;
        __syncthreads();  // previous iteration's PV reads (and Q-load writes) done

        // Load K tile transposed (both halves)
        for (int e = tid; e < BN * 32; e += 256) {
            int s = e >> 5;
            int c4 = e & 31;
            float4 val = *(const float4*)(kh + (size_t)(kbase + s) * 2 * HD + c4 * 4);
            float* dst = (c4 < 16) ? sKP1 : sKP2;
            int d0 = (c4 & 15) * 4;
            dst[(d0 + 0) * PITCH + s] = val.x;
            dst[(d0 + 1) * PITCH + s] = val.y;
            dst[(d0 + 2) * PITCH + s] = val.z;
            dst[(d0 + 3) * PITCH + s] = val.w;
        }
        // Load V tile (natural layout)
        for (int e = tid; e < BN * 16; e += 256) {
            int s = e >> 4;
            int c4 = e & 15;
            *(float4*)(sV + s * HD + c4 * 4) =
                *(const float4*)(vh + (size_t)(kbase + s) * HD + c4 * 4);
        }
        __syncthreads();

        // S = Q K^T for both halves (already in log2-softmax domain via C)
        float s1[4][4] = {}, s2[4][4] = {};
#pragma unroll 8
        for (int d = 0; d < HD; d++) {
            float a1[4], a2[4], b1[4], b2[4];
#pragma unroll
            for (int i = 0; i < 4; i++) {
                a1[i] = sQ1[d * PITCH + ty * 4 + i];
                a2[i] = sQ2[d * PITCH + ty * 4 + i];
            }
#pragma unroll
            for (int j = 0; j < 4; j++) {
                b1[j] = sKP1[d * PITCH + tx + 16 * j];
                b2[j] = sKP2[d * PITCH + tx + 16 * j];
            }
#pragma unroll
            for (int i = 0; i < 4; i++)
#pragma unroll
                for (int j = 0; j < 4; j++) {
                    s1[i][j] += a1[i] * b1[j];
                    s2[i][j] += a2[i] * b2[j];
                }
        }

        // Online softmax for both halves (p values left in s1/s2 registers)
#pragma unroll
        for (int i = 0; i < 4; i++) {
            // half 1
            float mx = fmaxf(fmaxf(s1[i][0], s1[i][1]), fmaxf(s1[i][2], s1[i][3]));
#pragma unroll
            for (int o = 8; o > 0; o >>= 1) mx = fmaxf(mx, __shfl_xor_sync(0xffffffffu, mx, o, 16));
            float mn = fmaxf(m1[i], mx);
            float f = ex2(m1[i] - mn);
            m1[i] = mn;
            float rs = 0.f;
#pragma unroll
            for (int j = 0; j < 4; j++) { float p = ex2(s1[i][j] - mn); s1[i][j] = p; rs += p; }
#pragma unroll
            for (int o = 8; o > 0; o >>= 1) rs += __shfl_xor_sync(0xffffffffu, rs, o, 16);
            l1[i] = l1[i] * f + rs;
#pragma unroll
            for (int j = 0; j < 4; j++) acc1[i][j] *= f;
            // half 2
            float mx2 = fmaxf(fmaxf(s2[i][0], s2[i][1]), fmaxf(s2[i][2], s2[i][3]));
#pragma unroll
            for (int o = 8; o > 0; o >>= 1) mx2 = fmaxf(mx2, __shfl_xor_sync(0xffffffffu, mx2, o, 16));
            float mn2 = fmaxf(m2[i], mx2);
            float f2 = ex2(m2[i] - mn2);
            m2[i] = mn2;
            float rs2 = 0.f;
#pragma unroll
            for (int j = 0; j < 4; j++) { float p = ex2(s2[i][j] - mn2); s2[i][j] = p; rs2 += p; }
#pragma unroll
            for (int o = 8; o > 0; o >>= 1) rs2 += __shfl_xor_sync(0xffffffffu, rs2, o, 16);
            l2[i] = l2[i] * f2 + rs2;
#pragma unroll
            for (int j = 0; j < 4; j++) acc2[i][j] *= f2;
        }

        __syncthreads();  // everyone done reading K before P overwrites it

        // Write P (transposed: [key][query]) into the K smem region
#pragma unroll
        for (int j = 0; j < 4; j++)
#pragma unroll
            for (int i = 0; i < 4; i++) {
                sKP1[(tx + 16 * j) * PITCH + ty * 4 + i] = s1[i][j];
                sKP2[(tx + 16 * j) * PITCH + ty * 4 + i] = s2[i][j];
            }
        __syncthreads();

        // acc += P V for both halves
#pragma unroll 4
        for (int kk = 0; kk < BN; kk++) {
            float p1[4], p2[4], vv[4];
#pragma unroll
            for (int i = 0; i < 4; i++) {
                p1[i] = sKP1[kk * PITCH + ty * 4 + i];
                p2[i] = sKP2[kk * PITCH + ty * 4 + i];
            }
#pragma unroll
            for (int j = 0; j < 4; j++) vv[j] = sV[kk * HD + tx + 16 * j];
#pragma unroll
            for (int i = 0; i < 4; i++)
#pragma unroll
                for (int j = 0; j < 4; j++) {
                    acc1[i][j] += p1[i] * vv[j];
                    acc2[i][j] += p2[i] * vv[j];
                }
        }
    }

    // Epilogue: combine halves, write raw output, accumulate per-head stats.
    const float lam = g_lam;
    float lsum = 0.f, lsq = 0.f;
    float* orow = out + ((size_t)h * SEQ + qbase) * HD;
#pragma unroll
    for (int i = 0; i < 4; i++) {
        float r1 = 1.f / l1[i];
        float r2 = lam / l2[i];
#pragma unroll
        for (int j = 0; j < 4; j++) {
            float o = acc1[i][j] * r1 - acc2[i][j] * r2;
            orow[(ty * 4 + i) * HD + tx + 16 * j] = o;
            lsum += o;
            lsq += o * o;
        }
    }
#pragma unroll
    for (int o = 16; o > 0; o >>= 1) {
        lsum += __shfl_xor_sync(0xffffffffu, lsum, o);
        lsq += __shfl_xor_sync(0xffffffffu, lsq, o);
    }
    __shared__ float red[16];
    int w = tid >> 5;
    if ((tid & 31) == 0) { red[w] = lsum; red[w + 8] = lsq; }
    __syncthreads();
    if (tid == 0) {
        float a = 0.f, b = 0.f;
#pragma unroll
        for (int i = 0; i < 8; i++) { a += red[i]; b += red[i + 8]; }
        atomicAdd(&g_sum[h], a);
        atomicAdd(&g_sumsq[h], b);
    }
}

// ---------------------------------------------------------------------------
// Kernel 2: per-head layernorm over (S, D), gamma/beta, final *0.2
// ---------------------------------------------------------------------------
__global__ void norm_kernel(float* __restrict__ out, const float* __restrict__ gamma,
                            const float* __restrict__ beta) {
    int i4 = blockIdx.x * blockDim.x + threadIdx.x;
    int idx = i4 * 4;
    int h = idx >> 17;  // S*D = 131072 = 2^17 elements per head
    int d = idx & (HD - 1);
    const float inv_n = 1.0f / (float)(SEQ * HD);
    float mean = g_sum[h] * inv_n;
    float var = g_sumsq[h] * inv_n - mean * mean;
    float is = rsqrtf(var + 1e-5f);
    float4 x = *(float4*)(out + idx);
    float4 g = *(const float4*)(gamma + h * HD + d);
    float4 b = *(const float4*)(beta + h * HD + d);
    x.x = ((x.x - mean) * is * g.x + b.x) * 0.2f;
    x.y = ((x.y - mean) * is * g.y + b.y) * 0.2f;
    x.z = ((x.z - mean) * is * g.z + b.z) * 0.2f;
    x.w = ((x.w - mean) * is * g.w + b.w) * 0.2f;
    *(float4*)(out + idx) = x;
}

// ---------------------------------------------------------------------------
extern "C" void kernel_launch(void* const* d_in, const int* in_sizes, int n_in,
                              void* d_out, int out_size) {
    const float* q = (const float*)d_in[0];
    const float* k = (const float*)d_in[1];
    const float* v = (const float*)d_in[2];
    const float* lq1 = (const float*)d_in[3];
    const float* lq2 = (const float*)d_in[4];
    const float* lk1 = (const float*)d_in[5];
    const float* lk2 = (const float*)d_in[6];
    const float* gamma = (const float*)d_in[7];
    const float* beta = (const float*)d_in[8];
    float* out = (float*)d_out;

    cudaFuncSetAttribute(attn_kernel, cudaFuncAttributeMaxDynamicSharedMemorySize, SMEM_BYTES);

    init_kernel<<<1, 32>>>(lq1, lq2, lk1, lk2);
    dim3 grid(SEQ / BM, NH);
    attn_kernel<<<grid, 256, SMEM_BYTES>>>(q, k, v, out);
    int total4 = NH * SEQ * HD / 4;
    norm_kernel<<<total4 / 256, 256>>>(out, gamma, beta);
}

// round 3
// speedup vs baseline: 3.1843x; 3.1843x over previous
#include <cuda_runtime.h>
#include <cstdint>

#define NH 16
#define SEQ 2048
#define HD 64
#define BM 128
#define BN 64
#define NT (SEQ / BN)
#define P68 68

// ---- SMEM layout (in floats) ----
// double-buffered K1,K2,VT: each 64 x 68
#define TILE_F (64 * P68)              // 4352
#define BUF_F (3 * TILE_F)             // 13056 per buffer
#define SK1(b) ((b) * BUF_F)
#define SK2(b) ((b) * BUF_F + TILE_F)
#define SVT(b) ((b) * BUF_F + 2 * TILE_F)
#define SP1 (2 * BUF_F)                // 26112 : P half-1 / Q1 staging / (unused)
#define SP2 (SP1 + 128 * P68)          // 34816 : P half-2 / Q2 staging / O2 exchange
#define SRED (SP2 + 128 * P68)         // 43520
#define SMEM_FLOATS (SRED + 16)
#define SMEM_BYTES (SMEM_FLOATS * 4)

__device__ float g_sum[NH];
__device__ float g_sumsq[NH];
__device__ float g_lam;

__device__ __forceinline__ float ex2(float x) {
    float r; asm("ex2.approx.ftz.f32 %0, %1;" : "=f"(r) : "f"(x)); return r;
}
__device__ __forceinline__ uint32_t totf(float x) {
    uint32_t r; asm("cvt.rna.tf32.f32 %0, %1;" : "=r"(r) : "f"(x)); return r;
}
__device__ __forceinline__ void mma8(float d[4], const uint32_t a[4], const uint32_t b[2]) {
    asm volatile(
        "mma.sync.aligned.m16n8k8.row.col.f32.tf32.tf32.f32 "
        "{%0,%1,%2,%3},{%4,%5,%6,%7},{%8,%9},{%0,%1,%2,%3};"
        : "+f"(d[0]), "+f"(d[1]), "+f"(d[2]), "+f"(d[3])
        : "r"(a[0]), "r"(a[1]), "r"(a[2]), "r"(a[3]), "r"(b[0]), "r"(b[1]));
}

// ---------------------------------------------------------------------------
__global__ void init_kernel(const float* __restrict__ lq1, const float* __restrict__ lq2,
                            const float* __restrict__ lk1, const float* __restrict__ lk2) {
    int t = threadIdx.x;
    if (t < NH) { g_sum[t] = 0.f; g_sumsq[t] = 0.f; }
    float a = lq1[t] * lk1[t] + lq1[t + 32] * lk1[t + 32];
    float b = lq2[t] * lk2[t] + lq2[t + 32] * lk2[t + 32];
#pragma unroll
    for (int o = 16; o > 0; o >>= 1) {
        a += __shfl_xor_sync(0xffffffffu, a, o);
        b += __shfl_xor_sync(0xffffffffu, b, o);
    }
    if (t == 0) g_lam = __expf(a) - __expf(b) + 0.8f;
}

// ---------------------------------------------------------------------------
__global__ void __launch_bounds__(256) attn_kernel(
    const float* __restrict__ q, const float* __restrict__ k,
    const float* __restrict__ v, float* __restrict__ out) {
    extern __shared__ float sm[];
    uint32_t* smu = (uint32_t*)sm;

    const int tid = threadIdx.x;
    const int w = tid >> 5;
    const int lane = tid & 31;
    const int lq = lane >> 2;   // quad id 0..7
    const int lt = lane & 3;    // thread-in-quad 0..3
    const int half2 = (w >= 4);
    const int wrow = (w & 3) * 32;   // warp's row base within the 128-row q tile
    const int h = blockIdx.y;
    const int qbase = blockIdx.x * BM;

    const float C = 0.18033688011112042f;  // (1/8)*log2(e)

    const float* qh = q + (size_t)h * SEQ * 2 * HD;
    const float* kh = k + (size_t)h * SEQ * 2 * HD;
    const float* vh = v + (size_t)h * SEQ * HD;

    // ---- stage Q (tf32, scaled) into SP1/SP2 region ----
    for (int e = tid; e < BM * 32; e += 256) {
        int c4 = e & 31;
        int r = e >> 5;
        float4 val = *(const float4*)(qh + (size_t)(qbase + r) * 2 * HD + c4 * 4);
        int base = (c4 < 16) ? SP1 : SP2;
        int d0 = (c4 & 15) * 4;
        uint32_t* dst = smu + base + r * P68 + d0;
        dst[0] = totf(val.x * C); dst[1] = totf(val.y * C);
        dst[2] = totf(val.z * C); dst[3] = totf(val.w * C);
    }

    // ---- load K/V tile 0 into buffer 0 ----
    {
        const int kbase = 0;
        for (int e = tid; e < BN * 32; e += 256) {
            int c4 = e & 31;
            int r = e >> 5;
            float4 val = *(const float4*)(kh + (size_t)(kbase + r) * 2 * HD + c4 * 4);
            int base = (c4 < 16) ? SK1(0) : SK2(0);
            int d0 = (c4 & 15) * 4;
            uint32_t* dst = smu + base + r * P68 + d0;
            dst[0] = totf(val.x); dst[1] = totf(val.y);
            dst[2] = totf(val.z); dst[3] = totf(val.w);
        }
        int k0 = (tid & 15) * 4;
        int d0 = (tid >> 4) * 4;
        float4 row[4];
#pragma unroll
        for (int i = 0; i < 4; i++)
            row[i] = *(const float4*)(vh + (size_t)(kbase + k0 + i) * HD + d0);
#pragma unroll
        for (int j = 0; j < 4; j++) {
            uint32_t* dst = smu + SVT(0) + (d0 + j) * P68 + k0;
            dst[0] = totf(((const float*)&row[0])[j]);
            dst[1] = totf(((const float*)&row[1])[j]);
            dst[2] = totf(((const float*)&row[2])[j]);
            dst[3] = totf(((const float*)&row[3])[j]);
        }
    }
    __syncthreads();

    // ---- extract Q fragments into registers ----
    uint32_t qa[2][8][4];
    {
        const uint32_t* sq = smu + (half2 ? SP2 : SP1);
#pragma unroll
        for (int m = 0; m < 2; m++)
#pragma unroll
            for (int kg = 0; kg < 8; kg++) {
                int r0 = wrow + m * 16 + lq;
                int c0 = kg * 8 + lt;
                qa[m][kg][0] = sq[r0 * P68 + c0];
                qa[m][kg][1] = sq[(r0 + 8) * P68 + c0];
                qa[m][kg][2] = sq[r0 * P68 + c0 + 4];
                qa[m][kg][3] = sq[(r0 + 8) * P68 + c0 + 4];
            }
    }

    float o[2][8][4] = {};
    float lrow[4] = {};     // [m*2 + rowhalf], per-lane partial softmax denominators
    const int sPbase = half2 ? SP2 : SP1;

    for (int t = 0; t < NT; t++) {
        if (t) __syncthreads();
        const int buf = t & 1;

        // ---- prefetch tile t+1 into buf^1 ----
        if (t + 1 < NT) {
            const int kbase = (t + 1) * BN;
            const int nb = buf ^ 1;
            for (int e = tid; e < BN * 32; e += 256) {
                int c4 = e & 31;
                int r = e >> 5;
                float4 val = *(const float4*)(kh + (size_t)(kbase + r) * 2 * HD + c4 * 4);
                int base = (c4 < 16) ? SK1(nb) : SK2(nb);
                int d0 = (c4 & 15) * 4;
                uint32_t* dst = smu + base + r * P68 + d0;
                dst[0] = totf(val.x); dst[1] = totf(val.y);
                dst[2] = totf(val.z); dst[3] = totf(val.w);
            }
            int k0 = (tid & 15) * 4;
            int d0 = (tid >> 4) * 4;
            float4 row[4];
#pragma unroll
            for (int i = 0; i < 4; i++)
                row[i] = *(const float4*)(vh + (size_t)(kbase + k0 + i) * HD + d0);
#pragma unroll
            for (int j = 0; j < 4; j++) {
                uint32_t* dst = smu + SVT(nb) + (d0 + j) * P68 + k0;
                dst[0] = totf(((const float*)&row[0])[j]);
                dst[1] = totf(((const float*)&row[1])[j]);
                dst[2] = totf(((const float*)&row[2])[j]);
                dst[3] = totf(((const float*)&row[3])[j]);
            }
        }

        // ---- QK + softmax, n-tile at a time ----
        const uint32_t* sk = smu + (half2 ? SK2(buf) : SK1(buf));
#pragma unroll
        for (int n = 0; n < 8; n++) {
            float s[2][4] = {};
#pragma unroll
            for (int kg = 0; kg < 8; kg++) {
                uint32_t b[2];
                const uint32_t* bp = sk + (n * 8 + lq) * P68 + kg * 8 + lt;
                b[0] = bp[0];
                b[1] = bp[4];
                mma8(s[0], qa[0][kg], b);
                mma8(s[1], qa[1][kg], b);
            }
#pragma unroll
            for (int m = 0; m < 2; m++) {
                float p0 = ex2(s[m][0]), p1 = ex2(s[m][1]);
                float p2 = ex2(s[m][2]), p3 = ex2(s[m][3]);
                lrow[m * 2 + 0] += p0 + p1;
                lrow[m * 2 + 1] += p2 + p3;
                int r0 = wrow + m * 16 + lq;
                uint32_t* pp = smu + sPbase + r0 * P68 + n * 8 + lt * 2;
                uint2 w0 = {totf(p0), totf(p1)};
                uint2 w1 = {totf(p2), totf(p3)};
                *(uint2*)pp = w0;
                *(uint2*)(pp + 8 * P68) = w1;
            }
        }
        __syncwarp();

        // ---- PV ----
        const uint32_t* svt = smu + SVT(buf);
        const uint32_t* sp = smu + sPbase;
#pragma unroll
        for (int kg = 0; kg < 8; kg++) {
            uint32_t a[2][4];
#pragma unroll
            for (int m = 0; m < 2; m++) {
                int r0 = wrow + m * 16 + lq;
                int c0 = kg * 8 + lt;
                a[m][0] = sp[r0 * P68 + c0];
                a[m][1] = sp[(r0 + 8) * P68 + c0];
                a[m][2] = sp[r0 * P68 + c0 + 4];
                a[m][3] = sp[(r0 + 8) * P68 + c0 + 4];
            }
#pragma unroll
            for (int n = 0; n < 8; n++) {
                uint32_t b[2];
                const uint32_t* bp = svt + (n * 8 + lq) * P68 + kg * 8 + lt;
                b[0] = bp[0];
                b[1] = bp[4];
                mma8(o[0][n], a[0], b);
                mma8(o[1][n], a[1], b);
            }
        }
    }

    // ---- reduce row denominators across each quad ----
#pragma unroll
    for (int i = 0; i < 4; i++) {
        lrow[i] += __shfl_xor_sync(0xffffffffu, lrow[i], 1);
        lrow[i] += __shfl_xor_sync(0xffffffffu, lrow[i], 2);
    }

    __syncthreads();  // all PV reads of P smem done before O2 exchange reuses it

    const float lam = g_lam;
    if (half2) {
        // write lam/l2-scaled O2 into SP2 region
#pragma unroll
        for (int m = 0; m < 2; m++) {
            float s0 = lam / lrow[m * 2 + 0];
            float s1 = lam / lrow[m * 2 + 1];
            int r0 = wrow + m * 16 + lq;
#pragma unroll
            for (int n = 0; n < 8; n++) {
                float* pp = sm + SP2 + r0 * P68 + n * 8 + lt * 2;
                pp[0] = o[m][n][0] * s0;
                pp[1] = o[m][n][1] * s0;
                pp[8 * P68] = o[m][n][2] * s1;
                pp[8 * P68 + 1] = o[m][n][3] * s1;
            }
        }
    }
    __syncthreads();

    float lsum = 0.f, lsq = 0.f;
    if (!half2) {
#pragma unroll
        for (int m = 0; m < 2; m++) {
            float r0s = 1.f / lrow[m * 2 + 0];
            float r1s = 1.f / lrow[m * 2 + 1];
            int r0 = wrow + m * 16 + lq;
            float* orow0 = out + ((size_t)h * SEQ + qbase + r0) * HD;
            float* orow1 = out + ((size_t)h * SEQ + qbase + r0 + 8) * HD;
#pragma unroll
            for (int n = 0; n < 8; n++) {
                const float* pp = sm + SP2 + r0 * P68 + n * 8 + lt * 2;
                float v0 = o[m][n][0] * r0s - pp[0];
                float v1 = o[m][n][1] * r0s - pp[1];
                float v2 = o[m][n][2] * r1s - pp[8 * P68];
                float v3 = o[m][n][3] * r1s - pp[8 * P68 + 1];
                int c = n * 8 + lt * 2;
                float2 t0 = {v0, v1};
                float2 t1 = {v2, v3};
                *(float2*)(orow0 + c) = t0;
                *(float2*)(orow1 + c) = t1;
                lsum += v0 + v1 + v2 + v3;
                lsq += v0 * v0 + v1 * v1 + v2 * v2 + v3 * v3;
            }
        }
#pragma unroll
        for (int off = 16; off > 0; off >>= 1) {
            lsum += __shfl_xor_sync(0xffffffffu, lsum, off);
            lsq += __shfl_xor_sync(0xffffffffu, lsq, off);
        }
        if (lane == 0) { sm[SRED + w] = lsum; sm[SRED + 4 + w] = lsq; }
    }
    __syncthreads();
    if (tid == 0) {
        float a = sm[SRED] + sm[SRED + 1] + sm[SRED + 2] + sm[SRED + 3];
        float b = sm[SRED + 4] + sm[SRED + 5] + sm[SRED + 6] + sm[SRED + 7];
        atomicAdd(&g_sum[h], a);
        atomicAdd(&g_sumsq[h], b);
    }
}

// ---------------------------------------------------------------------------
__global__ void norm_kernel(float* __restrict__ out, const float* __restrict__ gamma,
                            const float* __restrict__ beta) {
    int i4 = blockIdx.x * blockDim.x + threadIdx.x;
    int idx = i4 * 4;
    int h = idx >> 17;
    int d = idx & (HD - 1);
    const float inv_n = 1.0f / (float)(SEQ * HD);
    float mean = g_sum[h] * inv_n;
    float var = g_sumsq[h] * inv_n - mean * mean;
    float is = rsqrtf(var + 1e-5f);
    float4 x = *(float4*)(out + idx);
    float4 g = *(const float4*)(gamma + h * HD + d);
    float4 b = *(const float4*)(beta + h * HD + d);
    x.x = ((x.x - mean) * is * g.x + b.x) * 0.2f;
    x.y = ((x.y - mean) * is * g.y + b.y) * 0.2f;
    x.z = ((x.z - mean) * is * g.z + b.z) * 0.2f;
    x.w = ((x.w - mean) * is * g.w + b.w) * 0.2f;
    *(float4*)(out + idx) = x;
}

// ---------------------------------------------------------------------------
extern "C" void kernel_launch(void* const* d_in, const int* in_sizes, int n_in,
                              void* d_out, int out_size) {
    const float* q = (const float*)d_in[0];
    const float* k = (const float*)d_in[1];
    const float* v = (const float*)d_in[2];
    const float* lq1 = (const float*)d_in[3];
    const float* lq2 = (const float*)d_in[4];
    const float* lk1 = (const float*)d_in[5];
    const float* lk2 = (const float*)d_in[6];
    const float* gamma = (const float*)d_in[7];
    const float* beta = (const float*)d_in[8];
    float* out = (float*)d_out;

    cudaFuncSetAttribute(attn_kernel, cudaFuncAttributeMaxDynamicSharedMemorySize, SMEM_BYTES);

    init_kernel<<<1, 32>>>(lq1, lq2, lk1, lk2);
    dim3 grid(SEQ / BM, NH);
    attn_kernel<<<grid, 256, SMEM_BYTES>>>(q, k, v, out);
    int total4 = NH * SEQ * HD / 4;
    norm_kernel<<<total4 / 256, 256>>>(out, gamma, beta);
}

// round 4
// speedup vs baseline: 6.1411x; 1.9286x over previous
#include <cuda_runtime.h>
#include <cuda_fp16.h>
#include <cstdint>

#define NH 16
#define SEQ 2048
#define HD 64
#define BM 128
#define BN 64
#define NT (SEQ / BN)

// row pitch: 72 halves = 36 u32 = 144 bytes (conflict-free: bank = 4*lq + lt)
#define PU 36        // pitch in u32 units
#define PF 72        // exchange pitch in f32 units

// ---- SMEM layout (bytes) ----
#define TILE_B (64 * 144)                 // 9216
#define BUF_B (3 * TILE_B)                // 27648
#define SK1_B(b) ((b) * BUF_B)
#define SK2_B(b) ((b) * BUF_B + TILE_B)
#define SVT_B(b) ((b) * BUF_B + 2 * TILE_B)
#define SP1_B (2 * BUF_B)                 // 55296, 128x144
#define SP2_B (SP1_B + 128 * 144)         // 73728
#define SRED_B (SP2_B + 128 * 144)        // 92160
#define SMEM_BYTES (SRED_B + 64)

__device__ float g_sum[NH];
__device__ float g_sumsq[NH];
__device__ float g_lam;

__device__ __forceinline__ float ex2(float x) {
    float r; asm("ex2.approx.ftz.f32 %0, %1;" : "=f"(r) : "f"(x)); return r;
}
__device__ __forceinline__ uint32_t pack2(float lo, float hi) {
    uint32_t r;  // cvt.rn.f16x2.f32 d, a, b -> d.hi = a, d.lo = b
    asm("cvt.rn.f16x2.f32 %0, %1, %2;" : "=r"(r) : "f"(hi), "f"(lo));
    return r;
}
__device__ __forceinline__ void mma16(float d[4], const uint32_t a[4], const uint32_t b[2]) {
    asm volatile(
        "mma.sync.aligned.m16n8k16.row.col.f32.f16.f16.f32 "
        "{%0,%1,%2,%3},{%4,%5,%6,%7},{%8,%9},{%0,%1,%2,%3};"
        : "+f"(d[0]), "+f"(d[1]), "+f"(d[2]), "+f"(d[3])
        : "r"(a[0]), "r"(a[1]), "r"(a[2]), "r"(a[3]), "r"(b[0]), "r"(b[1]));
}

// ---------------------------------------------------------------------------
__global__ void init_kernel(const float* __restrict__ lq1, const float* __restrict__ lq2,
                            const float* __restrict__ lk1, const float* __restrict__ lk2) {
    int t = threadIdx.x;
    if (t < NH) { g_sum[t] = 0.f; g_sumsq[t] = 0.f; }
    float a = lq1[t] * lk1[t] + lq1[t + 32] * lk1[t + 32];
    float b = lq2[t] * lk2[t] + lq2[t + 32] * lk2[t + 32];
#pragma unroll
    for (int o = 16; o > 0; o >>= 1) {
        a += __shfl_xor_sync(0xffffffffu, a, o);
        b += __shfl_xor_sync(0xffffffffu, b, o);
    }
    if (t == 0) g_lam = __expf(a) - __expf(b) + 0.8f;
}

// ---------------------------------------------------------------------------
__global__ void __launch_bounds__(256, 2) attn_kernel(
    const float* __restrict__ q, const float* __restrict__ k,
    const float* __restrict__ v, float* __restrict__ out) {
    extern __shared__ char smc[];
    uint32_t* smu = (uint32_t*)smc;
    float* smf = (float*)smc;

    const int tid = threadIdx.x;
    const int w = tid >> 5;
    const int lane = tid & 31;
    const int lq = lane >> 2;
    const int lt = lane & 3;
    const int half2w = (w >= 4);
    const int wrow = (w & 3) * 32;
    const int h = blockIdx.y;
    const int qbase = blockIdx.x * BM;

    const float C = 0.18033688011112042f;  // (1/8)*log2(e)

    const float* qh = q + (size_t)h * SEQ * 2 * HD;
    const float* kh = k + (size_t)h * SEQ * 2 * HD;
    const float* vh = v + (size_t)h * SEQ * HD;

    // ---- stage Q (fp16, scaled) into P1/P2 regions ----
    for (int e = tid; e < BM * 32; e += 256) {
        int c4 = e & 31;
        int r = e >> 5;
        float4 val = *(const float4*)(qh + (size_t)(qbase + r) * 2 * HD + c4 * 4);
        int baseu = ((c4 < 16) ? SP1_B : SP2_B) >> 2;
        int d0 = (c4 & 15) * 4;
        uint2 pk = {pack2(val.x * C, val.y * C), pack2(val.z * C, val.w * C)};
        *(uint2*)(smu + baseu + r * PU + (d0 >> 1)) = pk;
    }

    // ---- load K/V tile 0 into buffer 0 ----
    {
        for (int e = tid; e < BN * 32; e += 256) {
            int c4 = e & 31;
            int r = e >> 5;
            float4 val = *(const float4*)(kh + (size_t)(r) * 2 * HD + c4 * 4);
            int baseu = ((c4 < 16) ? SK1_B(0) : SK2_B(0)) >> 2;
            int d0 = (c4 & 15) * 4;
            uint2 pk = {pack2(val.x, val.y), pack2(val.z, val.w)};
            *(uint2*)(smu + baseu + r * PU + (d0 >> 1)) = pk;
        }
        int k0 = (tid & 15) * 4;
        int d0 = (tid >> 4) * 4;
        float4 row[4];
#pragma unroll
        for (int i = 0; i < 4; i++)
            row[i] = *(const float4*)(vh + (size_t)(k0 + i) * HD + d0);
#pragma unroll
        for (int j = 0; j < 4; j++) {
            uint2 pk = {pack2(((const float*)&row[0])[j], ((const float*)&row[1])[j]),
                        pack2(((const float*)&row[2])[j], ((const float*)&row[3])[j])};
            *(uint2*)(smu + (SVT_B(0) >> 2) + (d0 + j) * PU + (k0 >> 1)) = pk;
        }
    }
    __syncthreads();

    // ---- extract Q fragments ----
    uint32_t qa[2][4][4];
    {
        const uint32_t* sq = smu + ((half2w ? SP2_B : SP1_B) >> 2);
#pragma unroll
        for (int m = 0; m < 2; m++)
#pragma unroll
            for (int kg = 0; kg < 4; kg++) {
                int r0 = wrow + m * 16 + lq;
                int c0 = kg * 8 + lt;
                qa[m][kg][0] = sq[r0 * PU + c0];
                qa[m][kg][1] = sq[(r0 + 8) * PU + c0];
                qa[m][kg][2] = sq[r0 * PU + c0 + 4];
                qa[m][kg][3] = sq[(r0 + 8) * PU + c0 + 4];
            }
    }

    float o[2][8][4] = {};
    float lrow[4] = {};
    const int sPu = (half2w ? SP2_B : SP1_B) >> 2;

    for (int t = 0; t < NT; t++) {
        if (t) __syncthreads();
        const int buf = t & 1;

        // ---- prefetch tile t+1 ----
        if (t + 1 < NT) {
            const int kbase = (t + 1) * BN;
            const int nb = buf ^ 1;
            for (int e = tid; e < BN * 32; e += 256) {
                int c4 = e & 31;
                int r = e >> 5;
                float4 val = *(const float4*)(kh + (size_t)(kbase + r) * 2 * HD + c4 * 4);
                int baseu = ((c4 < 16) ? SK1_B(nb) : SK2_B(nb)) >> 2;
                int d0 = (c4 & 15) * 4;
                uint2 pk = {pack2(val.x, val.y), pack2(val.z, val.w)};
                *(uint2*)(smu + baseu + r * PU + (d0 >> 1)) = pk;
            }
            int k0 = (tid & 15) * 4;
            int d0 = (tid >> 4) * 4;
            float4 row[4];
#pragma unroll
            for (int i = 0; i < 4; i++)
                row[i] = *(const float4*)(vh + (size_t)(kbase + k0 + i) * HD + d0);
#pragma unroll
            for (int j = 0; j < 4; j++) {
                uint2 pk = {pack2(((const float*)&row[0])[j], ((const float*)&row[1])[j]),
                            pack2(((const float*)&row[2])[j], ((const float*)&row[3])[j])};
                *(uint2*)(smu + (SVT_B(nb) >> 2) + (d0 + j) * PU + (k0 >> 1)) = pk;
            }
        }

        // ---- QK + softmax ----
        const uint32_t* sk = smu + ((half2w ? SK2_B(buf) : SK1_B(buf)) >> 2);
#pragma unroll
        for (int n = 0; n < 8; n++) {
            float s[2][4] = {};
#pragma unroll
            for (int kg = 0; kg < 4; kg++) {
                uint32_t b[2];
                const uint32_t* bp = sk + (n * 8 + lq) * PU + kg * 8 + lt;
                b[0] = bp[0];
                b[1] = bp[4];
                mma16(s[0], qa[0][kg], b);
                mma16(s[1], qa[1][kg], b);
            }
#pragma unroll
            for (int m = 0; m < 2; m++) {
                float p0 = ex2(s[m][0]), p1 = ex2(s[m][1]);
                float p2 = ex2(s[m][2]), p3 = ex2(s[m][3]);
                lrow[m * 2 + 0] += p0 + p1;
                lrow[m * 2 + 1] += p2 + p3;
                int r0 = wrow + m * 16 + lq;
                smu[sPu + r0 * PU + n * 4 + lt] = pack2(p0, p1);
                smu[sPu + (r0 + 8) * PU + n * 4 + lt] = pack2(p2, p3);
            }
        }
        __syncwarp();

        // ---- PV ----
        const uint32_t* svt = smu + (SVT_B(buf) >> 2);
        const uint32_t* sp = smu + sPu;
#pragma unroll
        for (int kg = 0; kg < 4; kg++) {
            uint32_t a[2][4];
#pragma unroll
            for (int m = 0; m < 2; m++) {
                int r0 = wrow + m * 16 + lq;
                int c0 = kg * 8 + lt;
                a[m][0] = sp[r0 * PU + c0];
                a[m][1] = sp[(r0 + 8) * PU + c0];
                a[m][2] = sp[r0 * PU + c0 + 4];
                a[m][3] = sp[(r0 + 8) * PU + c0 + 4];
            }
#pragma unroll
            for (int n = 0; n < 8; n++) {
                uint32_t b[2];
                const uint32_t* bp = svt + (n * 8 + lq) * PU + kg * 8 + lt;
                b[0] = bp[0];
                b[1] = bp[4];
                mma16(o[0][n], a[0], b);
                mma16(o[1][n], a[1], b);
            }
        }
    }

    // ---- quad-reduce softmax denominators ----
#pragma unroll
    for (int i = 0; i < 4; i++) {
        lrow[i] += __shfl_xor_sync(0xffffffffu, lrow[i], 1);
        lrow[i] += __shfl_xor_sync(0xffffffffu, lrow[i], 2);
    }

    __syncthreads();

    const float lam = g_lam;
    float* ex = smf + (SP1_B >> 2);  // 128 rows x PF f32 (spans P1+P2)
    if (half2w) {
#pragma unroll
        for (int m = 0; m < 2; m++) {
            float s0 = lam / lrow[m * 2 + 0];
            float s1 = lam / lrow[m * 2 + 1];
            int r0 = wrow + m * 16 + lq;
#pragma unroll
            for (int n = 0; n < 8; n++) {
                float* pp = ex + r0 * PF + n * 8 + lt * 2;
                pp[0] = o[m][n][0] * s0;
                pp[1] = o[m][n][1] * s0;
                pp[8 * PF] = o[m][n][2] * s1;
                pp[8 * PF + 1] = o[m][n][3] * s1;
            }
        }
    }
    __syncthreads();

    if (!half2w) {
        float lsum = 0.f, lsq = 0.f;
#pragma unroll
        for (int m = 0; m < 2; m++) {
            float r0s = 1.f / lrow[m * 2 + 0];
            float r1s = 1.f / lrow[m * 2 + 1];
            int r0 = wrow + m * 16 + lq;
            float* orow0 = out + ((size_t)h * SEQ + qbase + r0) * HD;
            float* orow1 = out + ((size_t)h * SEQ + qbase + r0 + 8) * HD;
#pragma unroll
            for (int n = 0; n < 8; n++) {
                const float* pp = ex + r0 * PF + n * 8 + lt * 2;
                float v0 = o[m][n][0] * r0s - pp[0];
                float v1 = o[m][n][1] * r0s - pp[1];
                float v2 = o[m][n][2] * r1s - pp[8 * PF];
                float v3 = o[m][n][3] * r1s - pp[8 * PF + 1];
                int c = n * 8 + lt * 2;
                float2 t0 = {v0, v1};
                float2 t1 = {v2, v3};
                *(float2*)(orow0 + c) = t0;
                *(float2*)(orow1 + c) = t1;
                lsum += v0 + v1 + v2 + v3;
                lsq += v0 * v0 + v1 * v1 + v2 * v2 + v3 * v3;
            }
        }
#pragma unroll
        for (int off = 16; off > 0; off >>= 1) {
            lsum += __shfl_xor_sync(0xffffffffu, lsum, off);
            lsq += __shfl_xor_sync(0xffffffffu, lsq, off);
        }
        if (lane == 0) { smf[(SRED_B >> 2) + w] = lsum; smf[(SRED_B >> 2) + 4 + w] = lsq; }
    }
    __syncthreads();
    if (tid == 0) {
        const float* rd = smf + (SRED_B >> 2);
        float a = rd[0] + rd[1] + rd[2] + rd[3];
        float b = rd[4] + rd[5] + rd[6] + rd[7];
        atomicAdd(&g_sum[h], a);
        atomicAdd(&g_sumsq[h], b);
    }
}

// ---------------------------------------------------------------------------
__global__ void norm_kernel(float* __restrict__ out, const float* __restrict__ gamma,
                            const float* __restrict__ beta) {
    int i4 = blockIdx.x * blockDim.x + threadIdx.x;
    int idx = i4 * 4;
    int h = idx >> 17;
    int d = idx & (HD - 1);
    const float inv_n = 1.0f / (float)(SEQ * HD);
    float mean = g_sum[h] * inv_n;
    float var = g_sumsq[h] * inv_n - mean * mean;
    float is = rsqrtf(var + 1e-5f);
    float4 x = *(float4*)(out + idx);
    float4 g = *(const float4*)(gamma + h * HD + d);
    float4 b = *(const float4*)(beta + h * HD + d);
    x.x = ((x.x - mean) * is * g.x + b.x) * 0.2f;
    x.y = ((x.y - mean) * is * g.y + b.y) * 0.2f;
    x.z = ((x.z - mean) * is * g.z + b.z) * 0.2f;
    x.w = ((x.w - mean) * is * g.w + b.w) * 0.2f;
    *(float4*)(out + idx) = x;
}

// ---------------------------------------------------------------------------
extern "C" void kernel_launch(void* const* d_in, const int* in_sizes, int n_in,
                              void* d_out, int out_size) {
    const float* q = (const float*)d_in[0];
    const float* k = (const float*)d_in[1];
    const float* v = (const float*)d_in[2];
    const float* lq1 = (const float*)d_in[3];
    const float* lq2 = (const float*)d_in[4];
    const float* lk1 = (const float*)d_in[5];
    const float* lk2 = (const float*)d_in[6];
    const float* gamma = (const float*)d_in[7];
    const float* beta = (const float*)d_in[8];
    float* out = (float*)d_out;

    cudaFuncSetAttribute(attn_kernel, cudaFuncAttributeMaxDynamicSharedMemorySize, SMEM_BYTES);

    init_kernel<<<1, 32>>>(lq1, lq2, lk1, lk2);
    dim3 grid(SEQ / BM, NH);
    attn_kernel<<<grid, 256, SMEM_BYTES>>>(q, k, v, out);
    int total4 = NH * SEQ * HD / 4;
    norm_kernel<<<total4 / 256, 256>>>(out, gamma, beta);
}

// round 5
// speedup vs baseline: 6.6010x; 1.0749x over previous
#include <cuda_runtime.h>
#include <cuda_fp16.h>
#include <cstdint>

#define NH 16
#define SEQ 2048
#define HD 64
#define BM 128
#define BN 64
#define NT (SEQ / BN)

// row pitch: 72 halves = 36 u32 = 144 bytes (conflict-free: bank = 4*lq + lt)
#define PU 36
#define PF 72

// ---- SMEM layout (bytes) ----
#define TILE_B (64 * 144)                 // 9216
#define BUF_B (3 * TILE_B)                // 27648
#define SK1_B(b) ((b) * BUF_B)
#define SK2_B(b) ((b) * BUF_B + TILE_B)
#define SVT_B(b) ((b) * BUF_B + 2 * TILE_B)
#define SRED_B (2 * BUF_B)                // 55296
#define SMEM_BYTES (SRED_B + 64)
// Q staging (pre-loop): Q1 at byte 0, Q2 at byte BUF_B (each 128*144)
// Epilogue exchange (post-loop): 128 rows x PF f32 at byte 0

__device__ float g_sum[NH];
__device__ float g_sumsq[NH];
__device__ float g_lam;

__device__ __forceinline__ float ex2(float x) {
    float r; asm("ex2.approx.ftz.f32 %0, %1;" : "=f"(r) : "f"(x)); return r;
}
__device__ __forceinline__ uint32_t pack2(float lo, float hi) {
    uint32_t r;
    asm("cvt.rn.f16x2.f32 %0, %1, %2;" : "=r"(r) : "f"(hi), "f"(lo));
    return r;
}
__device__ __forceinline__ void mma16(float d[4], const uint32_t a[4], const uint32_t b[2]) {
    asm volatile(
        "mma.sync.aligned.m16n8k16.row.col.f32.f16.f16.f32 "
        "{%0,%1,%2,%3},{%4,%5,%6,%7},{%8,%9},{%0,%1,%2,%3};"
        : "+f"(d[0]), "+f"(d[1]), "+f"(d[2]), "+f"(d[3])
        : "r"(a[0]), "r"(a[1]), "r"(a[2]), "r"(a[3]), "r"(b[0]), "r"(b[1]));
}

// ---------------------------------------------------------------------------
__global__ void init_kernel(const float* __restrict__ lq1, const float* __restrict__ lq2,
                            const float* __restrict__ lk1, const float* __restrict__ lk2) {
    int t = threadIdx.x;
    if (t < NH) { g_sum[t] = 0.f; g_sumsq[t] = 0.f; }
    float a = lq1[t] * lk1[t] + lq1[t + 32] * lk1[t + 32];
    float b = lq2[t] * lk2[t] + lq2[t + 32] * lk2[t + 32];
#pragma unroll
    for (int o = 16; o > 0; o >>= 1) {
        a += __shfl_xor_sync(0xffffffffu, a, o);
        b += __shfl_xor_sync(0xffffffffu, b, o);
    }
    if (t == 0) g_lam = __expf(a) - __expf(b) + 0.8f;
}

// ---------------------------------------------------------------------------
__global__ void __launch_bounds__(256, 2) attn_kernel(
    const float* __restrict__ q, const float* __restrict__ k,
    const float* __restrict__ v, float* __restrict__ out) {
    extern __shared__ char smc[];
    uint32_t* smu = (uint32_t*)smc;
    float* smf = (float*)smc;

    const int tid = threadIdx.x;
    const int w = tid >> 5;
    const int lane = tid & 31;
    const int lq = lane >> 2;
    const int lt = lane & 3;
    const int half2w = (w >= 4);
    const int wrow = (w & 3) * 32;
    const int h = blockIdx.y;
    const int qbase = blockIdx.x * BM;

    const float C = 0.18033688011112042f;  // (1/8)*log2(e)

    const float* qh = q + (size_t)h * SEQ * 2 * HD;
    const float* kh = k + (size_t)h * SEQ * 2 * HD;
    const float* vh = v + (size_t)h * SEQ * HD;

    // ---- stage Q (fp16, scaled): Q1 at byte 0, Q2 at byte BUF_B ----
    for (int e = tid; e < BM * 32; e += 256) {
        int c4 = e & 31;
        int r = e >> 5;
        float4 val = *(const float4*)(qh + (size_t)(qbase + r) * 2 * HD + c4 * 4);
        int baseu = ((c4 < 16) ? 0 : BUF_B) >> 2;
        int d0 = (c4 & 15) * 4;
        uint2 pk = {pack2(val.x * C, val.y * C), pack2(val.z * C, val.w * C)};
        *(uint2*)(smu + baseu + r * PU + (d0 >> 1)) = pk;
    }
    __syncthreads();

    // ---- extract Q fragments ----
    uint32_t qa[2][4][4];
    {
        const uint32_t* sq = smu + ((half2w ? BUF_B : 0) >> 2);
#pragma unroll
        for (int m = 0; m < 2; m++)
#pragma unroll
            for (int kg = 0; kg < 4; kg++) {
                int r0 = wrow + m * 16 + lq;
                int c0 = kg * 8 + lt;
                qa[m][kg][0] = sq[r0 * PU + c0];
                qa[m][kg][1] = sq[(r0 + 8) * PU + c0];
                qa[m][kg][2] = sq[r0 * PU + c0 + 4];
                qa[m][kg][3] = sq[(r0 + 8) * PU + c0 + 4];
            }
    }
    __syncthreads();

    // ---- load K/V tile 0 into buffer 0 ----
    {
        for (int e = tid; e < BN * 32; e += 256) {
            int c4 = e & 31;
            int r = e >> 5;
            float4 val = *(const float4*)(kh + (size_t)(r) * 2 * HD + c4 * 4);
            int baseu = ((c4 < 16) ? SK1_B(0) : SK2_B(0)) >> 2;
            int d0 = (c4 & 15) * 4;
            uint2 pk = {pack2(val.x, val.y), pack2(val.z, val.w)};
            *(uint2*)(smu + baseu + r * PU + (d0 >> 1)) = pk;
        }
        int k0 = (tid & 15) * 4;
        int d0 = (tid >> 4) * 4;
        float4 row[4];
#pragma unroll
        for (int i = 0; i < 4; i++)
            row[i] = *(const float4*)(vh + (size_t)(k0 + i) * HD + d0);
#pragma unroll
        for (int j = 0; j < 4; j++) {
            uint2 pk = {pack2(((const float*)&row[0])[j], ((const float*)&row[1])[j]),
                        pack2(((const float*)&row[2])[j], ((const float*)&row[3])[j])};
            *(uint2*)(smu + (SVT_B(0) >> 2) + (d0 + j) * PU + (k0 >> 1)) = pk;
        }
    }

    float o[2][8][4] = {};
    float lrow[4] = {};

    for (int t = 0; t < NT; t++) {
        __syncthreads();
        const int buf = t & 1;

        // ---- prefetch tile t+1 ----
        if (t + 1 < NT) {
            const int kbase = (t + 1) * BN;
            const int nb = buf ^ 1;
            for (int e = tid; e < BN * 32; e += 256) {
                int c4 = e & 31;
                int r = e >> 5;
                float4 val = *(const float4*)(kh + (size_t)(kbase + r) * 2 * HD + c4 * 4);
                int baseu = ((c4 < 16) ? SK1_B(nb) : SK2_B(nb)) >> 2;
                int d0 = (c4 & 15) * 4;
                uint2 pk = {pack2(val.x, val.y), pack2(val.z, val.w)};
                *(uint2*)(smu + baseu + r * PU + (d0 >> 1)) = pk;
            }
            int k0 = (tid & 15) * 4;
            int d0 = (tid >> 4) * 4;
            float4 row[4];
#pragma unroll
            for (int i = 0; i < 4; i++)
                row[i] = *(const float4*)(vh + (size_t)(kbase + k0 + i) * HD + d0);
#pragma unroll
            for (int j = 0; j < 4; j++) {
                uint2 pk = {pack2(((const float*)&row[0])[j], ((const float*)&row[1])[j]),
                            pack2(((const float*)&row[2])[j], ((const float*)&row[3])[j])};
                *(uint2*)(smu + (SVT_B(nb) >> 2) + (d0 + j) * PU + (k0 >> 1)) = pk;
            }
        }

        const uint32_t* sk = smu + ((half2w ? SK2_B(buf) : SK1_B(buf)) >> 2);
        const uint32_t* svt = smu + (SVT_B(buf) >> 2);

        // ---- per k-group: QK (two n-tiles) -> softmax -> P in regs -> PV ----
#pragma unroll
        for (int kg = 0; kg < 4; kg++) {
            uint32_t pa[2][4];
#pragma unroll
            for (int p = 0; p < 2; p++) {
                const int n = kg * 2 + p;
                float s[2][4] = {};
#pragma unroll
                for (int kg2 = 0; kg2 < 4; kg2++) {
                    uint32_t b[2];
                    const uint32_t* bp = sk + (n * 8 + lq) * PU + kg2 * 8 + lt;
                    b[0] = bp[0];
                    b[1] = bp[4];
                    mma16(s[0], qa[0][kg2], b);
                    mma16(s[1], qa[1][kg2], b);
                }
#pragma unroll
                for (int m = 0; m < 2; m++) {
                    float p0 = ex2(s[m][0]), p1 = ex2(s[m][1]);
                    float p2 = ex2(s[m][2]), p3 = ex2(s[m][3]);
                    lrow[m * 2 + 0] += p0 + p1;
                    lrow[m * 2 + 1] += p2 + p3;
                    pa[m][p * 2 + 0] = pack2(p0, p1);   // a0 / a2
                    pa[m][p * 2 + 1] = pack2(p2, p3);   // a1 / a3
                }
            }
            // NOTE: pa[m] = {a0,a1,a2,a3} with a0=rows lq cols 2lt, a1=rows lq+8,
            // a2/a3 = cols +8 — matches A-fragment of m16n8k16 exactly.
#pragma unroll
            for (int n = 0; n < 8; n++) {
                uint32_t b[2];
                const uint32_t* bp = svt + (n * 8 + lq) * PU + kg * 8 + lt;
                b[0] = bp[0];
                b[1] = bp[4];
                mma16(o[0][n], pa[0], b);
                mma16(o[1][n], pa[1], b);
            }
        }
    }

    // ---- quad-reduce softmax denominators ----
#pragma unroll
    for (int i = 0; i < 4; i++) {
        lrow[i] += __shfl_xor_sync(0xffffffffu, lrow[i], 1);
        lrow[i] += __shfl_xor_sync(0xffffffffu, lrow[i], 2);
    }

    __syncthreads();

    const float lam = g_lam;
    float* exg = smf;  // epilogue exchange: 128 rows x PF f32 at byte 0
    if (half2w) {
#pragma unroll
        for (int m = 0; m < 2; m++) {
            float s0 = lam / lrow[m * 2 + 0];
            float s1 = lam / lrow[m * 2 + 1];
            int r0 = wrow + m * 16 + lq;
#pragma unroll
            for (int n = 0; n < 8; n++) {
                float* pp = exg + r0 * PF + n * 8 + lt * 2;
                pp[0] = o[m][n][0] * s0;
                pp[1] = o[m][n][1] * s0;
                pp[8 * PF] = o[m][n][2] * s1;
                pp[8 * PF + 1] = o[m][n][3] * s1;
            }
        }
    }
    __syncthreads();

    if (!half2w) {
        float lsum = 0.f, lsq = 0.f;
#pragma unroll
        for (int m = 0; m < 2; m++) {
            float r0s = 1.f / lrow[m * 2 + 0];
            float r1s = 1.f / lrow[m * 2 + 1];
            int r0 = wrow + m * 16 + lq;
            float* orow0 = out + ((size_t)h * SEQ + qbase + r0) * HD;
            float* orow1 = out + ((size_t)h * SEQ + qbase + r0 + 8) * HD;
#pragma unroll
            for (int n = 0; n < 8; n++) {
                const float* pp = exg + r0 * PF + n * 8 + lt * 2;
                float v0 = o[m][n][0] * r0s - pp[0];
                float v1 = o[m][n][1] * r0s - pp[1];
                float v2 = o[m][n][2] * r1s - pp[8 * PF];
                float v3 = o[m][n][3] * r1s - pp[8 * PF + 1];
                int c = n * 8 + lt * 2;
                float2 t0 = {v0, v1};
                float2 t1 = {v2, v3};
                *(float2*)(orow0 + c) = t0;
                *(float2*)(orow1 + c) = t1;
                lsum += v0 + v1 + v2 + v3;
                lsq += v0 * v0 + v1 * v1 + v2 * v2 + v3 * v3;
            }
        }
#pragma unroll
        for (int off = 16; off > 0; off >>= 1) {
            lsum += __shfl_xor_sync(0xffffffffu, lsum, off);
            lsq += __shfl_xor_sync(0xffffffffu, lsq, off);
        }
        if (lane == 0) { smf[(SRED_B >> 2) + w] = lsum; smf[(SRED_B >> 2) + 4 + w] = lsq; }
    }
    __syncthreads();
    if (tid == 0) {
        const float* rd = smf + (SRED_B >> 2);
        float a = rd[0] + rd[1] + rd[2] + rd[3];
        float b = rd[4] + rd[5] + rd[6] + rd[7];
        atomicAdd(&g_sum[h], a);
        atomicAdd(&g_sumsq[h], b);
    }
}

// ---------------------------------------------------------------------------
__global__ void norm_kernel(float* __restrict__ out, const float* __restrict__ gamma,
                            const float* __restrict__ beta) {
    int i4 = blockIdx.x * blockDim.x + threadIdx.x;
    int idx = i4 * 4;
    int h = idx >> 17;
    int d = idx & (HD - 1);
    const float inv_n = 1.0f / (float)(SEQ * HD);
    float mean = g_sum[h] * inv_n;
    float var = g_sumsq[h] * inv_n - mean * mean;
    float is = rsqrtf(var + 1e-5f);
    float4 x = *(float4*)(out + idx);
    float4 g = *(const float4*)(gamma + h * HD + d);
    float4 b = *(const float4*)(beta + h * HD + d);
    x.x = ((x.x - mean) * is * g.x + b.x) * 0.2f;
    x.y = ((x.y - mean) * is * g.y + b.y) * 0.2f;
    x.z = ((x.z - mean) * is * g.z + b.z) * 0.2f;
    x.w = ((x.w - mean) * is * g.w + b.w) * 0.2f;
    *(float4*)(out + idx) = x;
}

// ---------------------------------------------------------------------------
extern "C" void kernel_launch(void* const* d_in, const int* in_sizes, int n_in,
                              void* d_out, int out_size) {
    const float* q = (const float*)d_in[0];
    const float* k = (const float*)d_in[1];
    const float* v = (const float*)d_in[2];
    const float* lq1 = (const float*)d_in[3];
    const float* lq2 = (const float*)d_in[4];
    const float* lk1 = (const float*)d_in[5];
    const float* lk2 = (const float*)d_in[6];
    const float* gamma = (const float*)d_in[7];
    const float* beta = (const float*)d_in[8];
    float* out = (float*)d_out;

    cudaFuncSetAttribute(attn_kernel, cudaFuncAttributeMaxDynamicSharedMemorySize, SMEM_BYTES);

    init_kernel<<<1, 32>>>(lq1, lq2, lk1, lk2);
    dim3 grid(SEQ / BM, NH);
    attn_kernel<<<grid, 256, SMEM_BYTES>>>(q, k, v, out);
    int total4 = NH * SEQ * HD / 4;
    norm_kernel<<<total4 / 256, 256>>>(out, gamma, beta);
}